// round 12
// baseline (speedup 1.0000x reference)
#include <cuda_runtime.h>
#include <math.h>

#define NB      148              // one block per SM, single wave
#define NTHR    512              // 16 warps, 4/SMSP
#define GPB     (NTHR / 8)       // 64 groups per block
#define NGROUPS (NB * GPB)       // 9472
#define NWARP   (NTHR / 32)      // 16

typedef unsigned long long ull;

// Per-block partials: [block][head][ s, acc[64] ]  (fixed softmax base = 0;
// per-head constant score offset cancels in A/S -> dropped entirely)
__device__ float g_part[NB][4][65];
__device__ unsigned g_done = 0;

// ---- packed f32x2 helpers (ptxas never auto-fuses FFMA2) --------------------
__device__ __forceinline__ ull pk2(float lo, float hi) {
    ull r; asm("mov.b64 %0,{%1,%2};" : "=l"(r) : "f"(lo), "f"(hi)); return r;
}
__device__ __forceinline__ void upk2(float& lo, float& hi, ull p) {
    asm("mov.b64 {%0,%1},%2;" : "=f"(lo), "=f"(hi) : "l"(p));
}
__device__ __forceinline__ ull fma2(ull a, ull b, ull c) {
    ull d; asm("fma.rn.f32x2 %0,%1,%2,%3;" : "=l"(d) : "l"(a), "l"(b), "l"(c)); return d;
}
__device__ __forceinline__ ull mul2(ull a, ull b) {
    ull d; asm("mul.rn.f32x2 %0,%1,%2;" : "=l"(d) : "l"(a), "l"(b)); return d;
}
__device__ __forceinline__ float ex2_ap(float x) {
    float y; asm("ex2.approx.f32 %0,%1;" : "=f"(y) : "f"(x)); return y;
}
__device__ __forceinline__ float rcp_ap(float x) {
    float y; asm("rcp.approx.f32 %0,%1;" : "=f"(y) : "f"(x)); return y;
}
// Raw full-warp butterfly shuffle: control flow is warp-uniform by
// construction (uniform trip counts), so no WARPSYNC envelope is needed.
__device__ __forceinline__ float shflx(float v, int off) {
    float d;
    asm volatile("shfl.sync.bfly.b32 %0,%1,%2,0x1f,0xffffffff;"
                 : "=f"(d) : "f"(v), "r"(off));
    return d;
}

// -----------------------------------------------------------------------------
// Single fused kernel: inline prep -> branch-free streaming exp-accumulate
// (uniform trip count, warp-convergent) -> block partial -> last block does
// final combine + projections.  8 lanes per point.
// silu computed tanh-FREE via measured-fast MUFU ops (ex2/rcp, rt 8):
//   z = -x*log2e (folded into W1/b1);  hid = (z * -ln2) * rcp(1 + ex2(z))
// -----------------------------------------------------------------------------
__global__ void __launch_bounds__(NTHR, 1)
main_kernel(const float* __restrict__ rr,
            const float* __restrict__ ri,
            const float* __restrict__ W1,
            const float* __restrict__ b1,
            const float* __restrict__ W2,
            const float* __restrict__ b2,
            const float* __restrict__ query,
            const float* __restrict__ ipw,   // in_proj_w (192,64)
            const float* __restrict__ ipb,   // in_proj_b (192)
            const float* __restrict__ opw,   // out_proj_w (64,64)
            const float* __restrict__ opb,   // out_proj_b (64)
            float* __restrict__ out,
            int N)
{
    __shared__ float qv[64];
    __shared__ float tt[4][64];
    __shared__ float sh_u[4][64];
    __shared__ float sh_acc[NWARP][4][64];
    __shared__ float sh_s[NWARP][4];

    const int tid  = threadIdx.x;
    const int lane = tid & 31;
    const int sub  = tid & 7;

    // scale = 1/sqrt(hd) * log2(e), folded into u so inner exp is bare ex2
    const float SC = 0.25f * 1.4426950408889634f;
    const float NL2E = -1.4426950408889634f;     // -log2(e), folded into W1/b1

    // ---- inline prep (every block redundantly; ~25K FMA, L2-resident) ------
    if (tid < 64) {
        float a = ipb[tid], a2 = 0.f;
        #pragma unroll 8
        for (int m = 0; m < 64; m += 2) {
            a  = fmaf(query[m],     ipw[tid * 64 + m],     a);
            a2 = fmaf(query[m + 1], ipw[tid * 64 + m + 1], a2);
        }
        qv[tid] = a + a2;
    }
    __syncthreads();
    if (tid < 256) {
        const int h = tid >> 6, j = tid & 63;
        float t = 0.f;
        #pragma unroll 8
        for (int d = 0; d < 16; d++)
            t = fmaf(qv[h * 16 + d], ipw[(64 + h * 16 + d) * 64 + j], t);
        tt[h][j] = t;
    }
    __syncthreads();
    if (tid < 256) {
        const int h = tid >> 6, j = tid & 63;
        float u = 0.f, u2 = 0.f;
        #pragma unroll 8
        for (int jj = 0; jj < 64; jj += 2) {
            u  = fmaf(tt[h][jj],     W2[jj * 64 + j],       u);
            u2 = fmaf(tt[h][jj + 1], W2[(jj + 1) * 64 + j], u2);
        }
        sh_u[h][j] = SC * (u + u2);
    }
    __syncthreads();

    // ---- per-lane packed constants (-log2e pre-folded into W1/b1) -----------
    const int j0 = sub * 8;
    ull w1ap[4], w1bp[4], b1p[4], u4p[4][4];
    #pragma unroll
    for (int k = 0; k < 4; k++) {
        const int j = j0 + 2 * k;
        w1ap[k] = pk2(NL2E * W1[2 * j],     NL2E * W1[2 * j + 2]);
        w1bp[k] = pk2(NL2E * W1[2 * j + 1], NL2E * W1[2 * j + 3]);
        b1p[k]  = pk2(NL2E * b1[j], NL2E * b1[j + 1]);
        #pragma unroll
        for (int h = 0; h < 4; h++) u4p[h][k] = pk2(sh_u[h][j], sh_u[h][j + 1]);
    }
    const ull negln2pk = pk2(-0.6931471805599453f, -0.6931471805599453f);
    const ull onepk    = pk2(1.0f, 1.0f);

    // ---- accumulators (fixed base: w = 2^sc, softmax shift-invariant) -------
    float s4[4] = {0.f, 0.f, 0.f, 0.f};
    ull accp[4][4];
    #pragma unroll
    for (int h = 0; h < 4; h++)
        #pragma unroll
        for (int k = 0; k < 4; k++) accp[h][k] = 0ull;

    // ---- streaming loop: UNIFORM trip count, fully warp-convergent -----------
    // Every group runs T iterations; out-of-range points are index-clamped and
    // their weight is predicated to 0 (exact: contributes nothing to s/acc).
    const int gid = blockIdx.x * GPB + (tid >> 3);
    const int T = (N + NGROUPS - 1) / NGROUPS;
    {
        int p = gid;
        int pc = (p < N) ? p : (N - 1);
        float r  = __ldg(rr + pc);
        float im = __ldg(ri + pc);
        for (int it = 0; it < T; it++) {
            const int pn = p + NGROUPS;
            const int pcn = (pn < N) ? pn : (N - 1);
            const float r_n  = __ldg(rr + pcn);
            const float im_n = __ldg(ri + pcn);
            const bool ok = (p < N);

            const ull rpk = pk2(r, r);
            const ull ipk = pk2(im, im);
            ull hid[4];
            ull partp[4] = {0ull, 0ull, 0ull, 0ull};
            #pragma unroll
            for (int k = 0; k < 4; k++) {
                // z = -x*log2e ; hid = silu(x) = x * 1/(1+2^z), x = z*(-ln2)
                ull z = fma2(rpk, w1ap[k], b1p[k]);
                z = fma2(ipk, w1bp[k], z);
                float z0, z1; upk2(z0, z1, z);
                const ull xpk = mul2(z, negln2pk);
                const ull epk = pk2(ex2_ap(z0), ex2_ap(z1));
                const ull den = fma2(epk, onepk, onepk);     // 1 + 2^z
                float d0, d1; upk2(d0, d1, den);
                const ull rc = pk2(rcp_ap(d0), rcp_ap(d1));
                hid[k] = mul2(xpk, rc);
                #pragma unroll
                for (int h = 0; h < 4; h++)
                    partp[h] = fma2(u4p[h][k], hid[k], partp[h]);
            }
            float sc[4];
            #pragma unroll
            for (int h = 0; h < 4; h++) { float a, b; upk2(a, b, partp[h]); sc[h] = a + b; }

            // full-warp butterfly over the 8 group lanes
            #pragma unroll
            for (int off = 1; off < 8; off <<= 1) {
                #pragma unroll
                for (int h = 0; h < 4; h++)
                    sc[h] += shflx(sc[h], off);
            }

            #pragma unroll
            for (int h = 0; h < 4; h++) {
                const float w = ok ? ex2_ap(sc[h]) : 0.f;   // selp, no branch
                s4[h] += w;
                const ull wpk = pk2(w, w);
                #pragma unroll
                for (int k = 0; k < 4; k++)
                    accp[h][k] = fma2(wpk, hid[k], accp[h][k]);
            }

            p = pn; r = r_n; im = im_n;
        }
    }

    // ---- combine 4 groups of this warp (plain sums; warp convergent) ---------
    #pragma unroll
    for (int off = 8; off <= 16; off <<= 1) {
        #pragma unroll
        for (int h = 0; h < 4; h++) {
            s4[h] += shflx(s4[h], off);
            #pragma unroll
            for (int k = 0; k < 4; k++) {
                float a, b; upk2(a, b, accp[h][k]);
                a += shflx(a, off);
                b += shflx(b, off);
                accp[h][k] = pk2(a, b);
            }
        }
    }

    // ---- block combine via shared ---------------------------------------------
    const int wid = tid >> 5;
    if (lane < 8) {
        #pragma unroll
        for (int h = 0; h < 4; h++) {
            #pragma unroll
            for (int k = 0; k < 4; k++) {
                float a, b; upk2(a, b, accp[h][k]);
                sh_acc[wid][h][lane * 8 + 2 * k]     = a;
                sh_acc[wid][h][lane * 8 + 2 * k + 1] = b;
            }
            if (lane == 0) sh_s[wid][h] = s4[h];
        }
    }
    __syncthreads();

    if (tid < 256) {
        const int h = tid >> 6;
        const int j = tid & 63;
        float A = 0.f;
        #pragma unroll
        for (int w = 0; w < NWARP; w++) A += sh_acc[w][h][j];
        g_part[blockIdx.x][h][1 + j] = A;
        if (j == 0) {
            float S = 0.f;
            #pragma unroll
            for (int w = 0; w < NWARP; w++) S += sh_s[w][h];
            g_part[blockIdx.x][h][0] = S;
        }
    }

    // ---- last block does the final combine + projections -----------------------
    __threadfence();
    __shared__ bool is_last;
    __shared__ float sh_p[4][64];
    __shared__ float sh_hbar[4][64];
    __shared__ float sh_pooled[64];
    __shared__ float sh_S[4];
    if (tid == 0) is_last = (atomicAdd(&g_done, 1) == NB - 1);
    __syncthreads();
    if (!is_last) return;
    if (tid == 0) g_done = 0;            // reset for next graph replay

    const int h = (tid >> 6) & 3;
    const int j = tid & 63;

    if (tid < 256) {
        float A = 0.f;
        #pragma unroll 4
        for (int b = 0; b < NB; b++) A += __ldg(&g_part[b][h][1 + j]);
        sh_hbar[h][j] = A;               // staging: raw acc sum
    } else if (tid < 260) {
        const int hh = tid - 256;
        float S = 0.f;
        #pragma unroll 4
        for (int b = 0; b < NB; b++) S += __ldg(&g_part[b][hh][0]);
        sh_S[hh] = S;
    }
    __syncthreads();
    if (tid < 256) sh_p[h][j] = sh_hbar[h][j] / sh_S[h];   // E[hidden] head h
    __syncthreads();

    if (tid < 256) {
        float hb = b2[j];
        #pragma unroll 8
        for (int m = 0; m < 64; m++) hb = fmaf(W2[j * 64 + m], sh_p[h][m], hb);
        sh_hbar[h][j] = hb;
    }
    __syncthreads();

    if (tid < 64) {
        const int e = tid, hh = tid >> 4;
        float pl = ipb[128 + e];
        #pragma unroll 8
        for (int jj = 0; jj < 64; jj++)
            pl = fmaf(ipw[(128 + e) * 64 + jj], sh_hbar[hh][jj], pl);
        sh_pooled[e] = pl;
    }
    __syncthreads();

    if (tid < 64) {
        float o = opb[tid];
        #pragma unroll 8
        for (int e = 0; e < 64; e++) o = fmaf(opw[tid * 64 + e], sh_pooled[e], o);
        out[tid] = o;
    }
}

// -----------------------------------------------------------------------------
extern "C" void kernel_launch(void* const* d_in, const int* in_sizes, int n_in,
                              void* d_out, int out_size)
{
    const float* rr    = (const float*)d_in[0];   // rho_real (1024*1024)
    const float* ri    = (const float*)d_in[1];   // rho_imag
    // d_in[2..5]: l_A, l_B, Z_A, Z_B — unused by the reference math
    const float* W1    = (const float*)d_in[6];   // (64,2)
    const float* b1    = (const float*)d_in[7];   // (64)
    const float* W2    = (const float*)d_in[8];   // (64,64)
    const float* b2    = (const float*)d_in[9];   // (64)
    const float* query = (const float*)d_in[10];  // (1,64)
    const float* ipw   = (const float*)d_in[11];  // (192,64)
    const float* ipb   = (const float*)d_in[12];  // (192)
    const float* opw   = (const float*)d_in[13];  // (64,64)
    const float* opb   = (const float*)d_in[14];  // (64)
    const int N = in_sizes[0];

    main_kernel<<<NB, NTHR>>>(rr, ri, W1, b1, W2, b2, query, ipw, ipb,
                              opw, opb, (float*)d_out, N);
}

// round 13
// speedup vs baseline: 1.2008x; 1.2008x over previous
#include <cuda_runtime.h>
#include <math.h>

#define NB      148              // one block per SM, single wave
#define NTHR    448              // 14 warps; 146 regs/thread budget
#define GPB     (NTHR / 8)       // 56 groups per block
#define NGROUPS (NB * GPB)       // 8288
#define NWARP   (NTHR / 32)      // 14

typedef unsigned long long ull;

// Per-block partials: [block][head][ s, acc[64] ]  (fixed softmax base = 0;
// per-head constant score offset cancels in A/S -> dropped entirely)
__device__ float g_part[NB][4][65];
__device__ unsigned g_done = 0;

// ---- packing via register-pair aliasing (NO asm movs) ------------------------
union F2 { ull u; float2 f; };
__device__ __forceinline__ ull PK(float a, float b) {
    F2 t; t.f.x = a; t.f.y = b; return t.u;
}
__device__ __forceinline__ float2 UPK(ull v) { F2 t; t.u = v; return t.f; }

__device__ __forceinline__ ull fma2(ull a, ull b, ull c) {
    ull d; asm("fma.rn.f32x2 %0,%1,%2,%3;" : "=l"(d) : "l"(a), "l"(b), "l"(c)); return d;
}
__device__ __forceinline__ float tanh_ap(float x) {
    float y; asm("tanh.approx.f32 %0,%1;" : "=f"(y) : "f"(x)); return y;
}
__device__ __forceinline__ float ex2_ap(float x) {
    float y; asm("ex2.approx.f32 %0,%1;" : "=f"(y) : "f"(x)); return y;
}
// Raw full-warp butterfly shuffle (control flow warp-uniform by construction)
__device__ __forceinline__ float shflx(float v, int off) {
    float d;
    asm volatile("shfl.sync.bfly.b32 %0,%1,%2,0x1f,0xffffffff;"
                 : "=f"(d) : "f"(v), "r"(off));
    return d;
}
// silu(x) = h + h*tanh(h) with h = x/2 (the 1/2 is pre-folded into W1/b1)
__device__ __forceinline__ ull silu2h(ull hpk) {
    float2 h = UPK(hpk);
    return fma2(hpk, PK(tanh_ap(h.x), tanh_ap(h.y)), hpk);
}

// -----------------------------------------------------------------------------
// Single fused kernel: inline prep -> streaming exp-accumulate with a
// guard-free main loop (TMAIN in-range for every group by construction) and
// one predicated tail iteration -> block partial -> last block final.
// 8 lanes per point.
// -----------------------------------------------------------------------------
__global__ void __launch_bounds__(NTHR, 1)
main_kernel(const float* __restrict__ rr,
            const float* __restrict__ ri,
            const float* __restrict__ W1,
            const float* __restrict__ b1,
            const float* __restrict__ W2,
            const float* __restrict__ b2,
            const float* __restrict__ query,
            const float* __restrict__ ipw,   // in_proj_w (192,64)
            const float* __restrict__ ipb,   // in_proj_b (192)
            const float* __restrict__ opw,   // out_proj_w (64,64)
            const float* __restrict__ opb,   // out_proj_b (64)
            float* __restrict__ out,
            int N)
{
    __shared__ float qv[64];
    __shared__ float tt[4][64];
    __shared__ float sh_u[4][64];
    __shared__ float sh_acc[NWARP][4][64];
    __shared__ float sh_s[NWARP][4];

    const int tid  = threadIdx.x;
    const int lane = tid & 31;
    const int sub  = tid & 7;

    // scale = 1/sqrt(hd) * log2(e), folded into u so inner exp is bare ex2
    const float SC = 0.25f * 1.4426950408889634f;

    // ---- inline prep (every block redundantly; ~25K FMA, L2-resident) ------
    if (tid < 64) {
        float a = ipb[tid], a2 = 0.f;
        #pragma unroll 8
        for (int m = 0; m < 64; m += 2) {
            a  = fmaf(query[m],     ipw[tid * 64 + m],     a);
            a2 = fmaf(query[m + 1], ipw[tid * 64 + m + 1], a2);
        }
        qv[tid] = a + a2;
    }
    __syncthreads();
    if (tid < 256) {
        const int h = tid >> 6, j = tid & 63;
        float t = 0.f;
        #pragma unroll 8
        for (int d = 0; d < 16; d++)
            t = fmaf(qv[h * 16 + d], ipw[(64 + h * 16 + d) * 64 + j], t);
        tt[h][j] = t;
    }
    __syncthreads();
    if (tid < 256) {
        const int h = tid >> 6, j = tid & 63;
        float u = 0.f, u2 = 0.f;
        #pragma unroll 8
        for (int jj = 0; jj < 64; jj += 2) {
            u  = fmaf(tt[h][jj],     W2[jj * 64 + j],       u);
            u2 = fmaf(tt[h][jj + 1], W2[(jj + 1) * 64 + j], u2);
        }
        sh_u[h][j] = SC * (u + u2);
    }
    __syncthreads();

    // ---- per-lane packed constants (0.5 silu factor pre-folded) -------------
    const int j0 = sub * 8;
    ull w1ap[4], w1bp[4], b1p[4], u4p[4][4];
    #pragma unroll
    for (int k = 0; k < 4; k++) {
        const int j = j0 + 2 * k;
        w1ap[k] = PK(0.5f * W1[2 * j],     0.5f * W1[2 * j + 2]);
        w1bp[k] = PK(0.5f * W1[2 * j + 1], 0.5f * W1[2 * j + 3]);
        b1p[k]  = PK(0.5f * b1[j], 0.5f * b1[j + 1]);
        #pragma unroll
        for (int h = 0; h < 4; h++) u4p[h][k] = PK(sh_u[h][j], sh_u[h][j + 1]);
    }

    // ---- accumulators (fixed base: w = 2^sc, softmax shift-invariant) -------
    float s4[4] = {0.f, 0.f, 0.f, 0.f};
    ull accp[4][4];
    #pragma unroll
    for (int h = 0; h < 4; h++)
        #pragma unroll
        for (int k = 0; k < 4; k++) accp[h][k] = 0ull;

    // point body: hidden + scores + group-reduce + exp-accumulate.
    // TAIL=0 instantiation has no guard instructions at all.
    #define BODY(rv, iv, WEXPR)                                                \
    {                                                                          \
        const ull rpk = PK((rv), (rv));                                        \
        const ull ipk = PK((iv), (iv));                                        \
        ull hid[4];                                                            \
        ull partp[4] = {0ull, 0ull, 0ull, 0ull};                               \
        _Pragma("unroll")                                                      \
        for (int k = 0; k < 4; k++) {                                          \
            ull hh = fma2(rpk, w1ap[k], b1p[k]);                               \
            hh = fma2(ipk, w1bp[k], hh);                                       \
            hid[k] = silu2h(hh);                                               \
            _Pragma("unroll")                                                  \
            for (int h = 0; h < 4; h++)                                        \
                partp[h] = fma2(u4p[h][k], hid[k], partp[h]);                  \
        }                                                                      \
        float sc[4];                                                           \
        _Pragma("unroll")                                                      \
        for (int h = 0; h < 4; h++) { float2 t = UPK(partp[h]); sc[h] = t.x + t.y; } \
        _Pragma("unroll")                                                      \
        for (int off = 1; off < 8; off <<= 1) {                                \
            _Pragma("unroll")                                                  \
            for (int h = 0; h < 4; h++)                                        \
                sc[h] += shflx(sc[h], off);                                    \
        }                                                                      \
        _Pragma("unroll")                                                      \
        for (int h = 0; h < 4; h++) {                                          \
            const float w = (WEXPR);                                           \
            s4[h] += w;                                                        \
            const ull wpk = PK(w, w);                                          \
            _Pragma("unroll")                                                  \
            for (int k = 0; k < 4; k++)                                        \
                accp[h][k] = fma2(wpk, hid[k], accp[h][k]);                    \
        }                                                                      \
    }

    // ---- guard-free main loop -------------------------------------------------
    // TMAIN = N/NGROUPS: for it < TMAIN, p = gid + it*NGROUPS < N for EVERY
    // group (max p = TMAIN*NGROUPS - 1 <= N-1). No bounds checks inside.
    const int gid = blockIdx.x * GPB + (tid >> 3);
    const int TMAIN = N / NGROUPS;
    {
        int p = gid;
        float r  = __ldg(rr + p);
        float im = __ldg(ri + p);
        #pragma unroll 2
        for (int it = 1; it <= TMAIN; it++) {
            // prefetch next (clamped only by min against N-1: 1 IMNMX)
            const int pn = min(p + NGROUPS, N - 1);
            const float r_n  = __ldg(rr + pn);
            const float im_n = __ldg(ri + pn);

            BODY(r, im, ex2_ap(sc[h]))

            p += NGROUPS; r = r_n; im = im_n;
        }
        // one predicated tail iteration covers the remainder (remainder <
        // NGROUPS). Uniform across the warp; w forced to 0 when out of range.
        {
            const bool ok = (p < N);
            const int pc = ok ? p : (N - 1);
            const float r_t  = __ldg(rr + pc);
            const float im_t = __ldg(ri + pc);
            BODY(r_t, im_t, ok ? ex2_ap(sc[h]) : 0.f)
        }
    }

    // ---- combine 4 groups of this warp (plain sums; warp convergent) ---------
    #pragma unroll
    for (int off = 8; off <= 16; off <<= 1) {
        #pragma unroll
        for (int h = 0; h < 4; h++) {
            s4[h] += shflx(s4[h], off);
            #pragma unroll
            for (int k = 0; k < 4; k++) {
                float2 t = UPK(accp[h][k]);
                t.x += shflx(t.x, off);
                t.y += shflx(t.y, off);
                accp[h][k] = PK(t.x, t.y);
            }
        }
    }

    // ---- block combine via shared ---------------------------------------------
    const int wid = tid >> 5;
    if (lane < 8) {
        #pragma unroll
        for (int h = 0; h < 4; h++) {
            #pragma unroll
            for (int k = 0; k < 4; k++) {
                float2 t = UPK(accp[h][k]);
                sh_acc[wid][h][lane * 8 + 2 * k]     = t.x;
                sh_acc[wid][h][lane * 8 + 2 * k + 1] = t.y;
            }
            if (lane == 0) sh_s[wid][h] = s4[h];
        }
    }
    __syncthreads();

    if (tid < 256) {
        const int h = tid >> 6;
        const int j = tid & 63;
        float A = 0.f;
        #pragma unroll
        for (int w = 0; w < NWARP; w++) A += sh_acc[w][h][j];
        g_part[blockIdx.x][h][1 + j] = A;
        if (j == 0) {
            float S = 0.f;
            #pragma unroll
            for (int w = 0; w < NWARP; w++) S += sh_s[w][h];
            g_part[blockIdx.x][h][0] = S;
        }
    }

    // ---- last block does the final combine + projections -----------------------
    __threadfence();
    __shared__ bool is_last;
    __shared__ float sh_p[4][64];
    __shared__ float sh_hbar[4][64];
    __shared__ float sh_pooled[64];
    __shared__ float sh_S[4];
    if (tid == 0) is_last = (atomicAdd(&g_done, 1) == NB - 1);
    __syncthreads();
    if (!is_last) return;
    if (tid == 0) g_done = 0;            // reset for next graph replay

    const int h = (tid >> 6) & 3;
    const int j = tid & 63;

    if (tid < 256) {
        float A = 0.f;
        #pragma unroll 4
        for (int b = 0; b < NB; b++) A += __ldg(&g_part[b][h][1 + j]);
        sh_hbar[h][j] = A;               // staging: raw acc sum
    } else if (tid < 260) {
        const int hh = tid - 256;
        float S = 0.f;
        #pragma unroll 4
        for (int b = 0; b < NB; b++) S += __ldg(&g_part[b][hh][0]);
        sh_S[hh] = S;
    }
    __syncthreads();
    if (tid < 256) sh_p[h][j] = sh_hbar[h][j] / sh_S[h];   // E[hidden] head h
    __syncthreads();

    if (tid < 256) {
        float hb = b2[j];
        #pragma unroll 8
        for (int m = 0; m < 64; m++) hb = fmaf(W2[j * 64 + m], sh_p[h][m], hb);
        sh_hbar[h][j] = hb;
    }
    __syncthreads();

    if (tid < 64) {
        const int e = tid, hh = tid >> 4;
        float pl = ipb[128 + e];
        #pragma unroll 8
        for (int jj = 0; jj < 64; jj++)
            pl = fmaf(ipw[(128 + e) * 64 + jj], sh_hbar[hh][jj], pl);
        sh_pooled[e] = pl;
    }
    __syncthreads();

    if (tid < 64) {
        float o = opb[tid];
        #pragma unroll 8
        for (int e = 0; e < 64; e++) o = fmaf(opw[tid * 64 + e], sh_pooled[e], o);
        out[tid] = o;
    }
}

// -----------------------------------------------------------------------------
extern "C" void kernel_launch(void* const* d_in, const int* in_sizes, int n_in,
                              void* d_out, int out_size)
{
    const float* rr    = (const float*)d_in[0];   // rho_real (1024*1024)
    const float* ri    = (const float*)d_in[1];   // rho_imag
    // d_in[2..5]: l_A, l_B, Z_A, Z_B — unused by the reference math
    const float* W1    = (const float*)d_in[6];   // (64,2)
    const float* b1    = (const float*)d_in[7];   // (64)
    const float* W2    = (const float*)d_in[8];   // (64,64)
    const float* b2    = (const float*)d_in[9];   // (64)
    const float* query = (const float*)d_in[10];  // (1,64)
    const float* ipw   = (const float*)d_in[11];  // (192,64)
    const float* ipb   = (const float*)d_in[12];  // (192)
    const float* opw   = (const float*)d_in[13];  // (64,64)
    const float* opb   = (const float*)d_in[14];  // (64)
    const int N = in_sizes[0];

    main_kernel<<<NB, NTHR>>>(rr, ri, W1, b1, W2, b2, query, ipw, ipb,
                              opw, opb, (float*)d_out, N);
}